// round 1
// baseline (speedup 1.0000x reference)
#include <cuda_runtime.h>
#include <cuda_bf16.h>
#include <math.h>

// ---------------- scratch (__device__ globals; no runtime allocation) ------
// xi layout: [T=512][B=128][3H=3072] fp32
__device__ float g_xi[(size_t)512 * 128 * 3072];
__device__ float g_h0[128 * 1024];
__device__ float g_h1[128 * 1024];

// ---------------- xi = x @ Wi + bi  (M=65536, N=3072, K=512) ---------------
// Block tile 64(m) x 64(n), K-chunks of 16, 256 threads, 4x4 microtile.
// Row m of xi corresponds to (t = m>>7, b = m&127); x is [B,T,512].
__global__ __launch_bounds__(256) void xi_gemm(
    const float* __restrict__ x, const float* __restrict__ Wi,
    const float* __restrict__ bi, float* __restrict__ xi)
{
    __shared__ float As[16][64];
    __shared__ float Bs[16][64];

    const int n0 = blockIdx.x * 64;
    const int m0 = blockIdx.y * 64;
    const int tx = threadIdx.x & 15;
    const int ty = threadIdx.x >> 4;

    float acc[4][4];
#pragma unroll
    for (int i = 0; i < 4; i++)
#pragma unroll
        for (int j = 0; j < 4; j++) acc[i][j] = 0.f;

    for (int k0 = 0; k0 < 512; k0 += 16) {
        // load A tile: 64 rows x 16 k, one float4 per thread
        {
            const int mloc = threadIdx.x >> 2;
            const int kk   = (threadIdx.x & 3) * 4;
            const int m = m0 + mloc;
            const int t = m >> 7;
            const int b = m & 127;
            const float4 v = *reinterpret_cast<const float4*>(
                &x[((size_t)b * 512 + t) * 512 + k0 + kk]);
            As[kk + 0][mloc] = v.x;
            As[kk + 1][mloc] = v.y;
            As[kk + 2][mloc] = v.z;
            As[kk + 3][mloc] = v.w;
        }
        // load B tile: 16 k x 64 n, one float4 per thread
        {
            const int kk   = threadIdx.x >> 4;
            const int nloc = (threadIdx.x & 15) * 4;
            const float4 v = *reinterpret_cast<const float4*>(
                &Wi[(size_t)(k0 + kk) * 3072 + n0 + nloc]);
            *reinterpret_cast<float4*>(&Bs[kk][nloc]) = v;
        }
        __syncthreads();

#pragma unroll
        for (int kk = 0; kk < 16; kk++) {
            float a[4], b4[4];
#pragma unroll
            for (int i = 0; i < 4; i++) a[i] = As[kk][ty * 4 + i];
#pragma unroll
            for (int j = 0; j < 4; j++) b4[j] = Bs[kk][tx * 4 + j];
#pragma unroll
            for (int i = 0; i < 4; i++)
#pragma unroll
                for (int j = 0; j < 4; j++) acc[i][j] += a[i] * b4[j];
        }
        __syncthreads();
    }

#pragma unroll
    for (int i = 0; i < 4; i++) {
        const int m = m0 + ty * 4 + i;
#pragma unroll
        for (int j = 0; j < 4; j++) {
            const int n = n0 + tx * 4 + j;
            xi[(size_t)m * 3072 + n] = acc[i][j] + bi[n];
        }
    }
}

// ---------------- zero initial hidden state --------------------------------
__global__ void zero_h(float* __restrict__ h)
{
    h[(size_t)blockIdx.x * 256 + threadIdx.x] = 0.f;
}

// ---------------- one GRU step: fused GEMM(h@Wh)+bias+gates+update ---------
// Tile: 32 batch x 32 hidden per block; grid = (H/32=32, B/32=4) = 128 blocks.
// 256 threads: tx = hidden-local, ty = batch sub-row; each thread does
// 4 batch rows x 3 gates accumulators over K=1024.
__global__ __launch_bounds__(256) void gru_step(
    const float* __restrict__ hsrc, float* __restrict__ hdst,
    const float* __restrict__ Wh, const float* __restrict__ bh,
    const float* __restrict__ xi_t)
{
    __shared__ float hs[32][33];   // [batch-local][k-local], padded
    __shared__ float ws[32][96];   // [k-local][gate*32 + hidden-local]

    const int j0 = blockIdx.x * 32;
    const int b0 = blockIdx.y * 32;
    const int tx = threadIdx.x & 31;   // hidden local
    const int ty = threadIdx.x >> 5;   // 0..7

    float acc[4][3];
#pragma unroll
    for (int i = 0; i < 4; i++)
#pragma unroll
        for (int g = 0; g < 3; g++) acc[i][g] = 0.f;

    for (int k0 = 0; k0 < 1024; k0 += 32) {
        // h tile: 32x32, coalesced over k
        for (int idx = threadIdx.x; idx < 32 * 32; idx += 256) {
            const int bl = idx >> 5;
            const int kk = idx & 31;
            hs[bl][kk] = hsrc[(size_t)(b0 + bl) * 1024 + k0 + kk];
        }
        // Wh tile: 32 k x (3 gates x 32 hidden)
        for (int idx = threadIdx.x; idx < 32 * 96; idx += 256) {
            const int kk = idx / 96;
            const int c  = idx % 96;
            const int g  = c >> 5;
            const int jl = c & 31;
            ws[kk][c] = Wh[(size_t)(k0 + kk) * 3072 + g * 1024 + j0 + jl];
        }
        __syncthreads();

#pragma unroll
        for (int kk = 0; kk < 32; kk++) {
            const float w0 = ws[kk][tx];
            const float w1 = ws[kk][32 + tx];
            const float w2 = ws[kk][64 + tx];
#pragma unroll
            for (int i = 0; i < 4; i++) {
                const float hv = hs[ty + 8 * i][kk];  // warp broadcast
                acc[i][0] += hv * w0;
                acc[i][1] += hv * w1;
                acc[i][2] += hv * w2;
            }
        }
        __syncthreads();
    }

    const int j = j0 + tx;
    const float bhr = bh[j];
    const float bhz = bh[1024 + j];
    const float bhn = bh[2048 + j];

#pragma unroll
    for (int i = 0; i < 4; i++) {
        const int b = b0 + ty + 8 * i;
        const float hr = acc[i][0] + bhr;
        const float hz = acc[i][1] + bhz;
        const float hn = acc[i][2] + bhn;

        const float ir  = xi_t[(size_t)b * 3072 + j];
        const float iz  = xi_t[(size_t)b * 3072 + 1024 + j];
        const float inn = xi_t[(size_t)b * 3072 + 2048 + j];

        const float r = 1.f / (1.f + expf(-(ir + hr)));
        const float z = 1.f / (1.f + expf(-(iz + hz)));
        const float n = tanhf(inn + r * hn);

        const float hprev = hsrc[(size_t)b * 1024 + j];
        hdst[(size_t)b * 1024 + j] = z * n + (1.f - z) * hprev;
    }
}

// ---------------- launch ----------------------------------------------------
extern "C" void kernel_launch(void* const* d_in, const int* in_sizes, int n_in,
                              void* d_out, int out_size)
{
    const float* x  = (const float*)d_in[0];
    const float* Wi = (const float*)d_in[1];
    const float* bi = (const float*)d_in[2];
    const float* Wh = (const float*)d_in[3];
    const float* bh = (const float*)d_in[4];
    float* out = (float*)d_out;

    float *xi_ptr, *h0_ptr, *h1_ptr;
    cudaGetSymbolAddress((void**)&xi_ptr, g_xi);
    cudaGetSymbolAddress((void**)&h0_ptr, g_h0);
    cudaGetSymbolAddress((void**)&h1_ptr, g_h1);

    // xi = x @ Wi + bi  for all timesteps
    xi_gemm<<<dim3(3072 / 64, 65536 / 64), 256>>>(x, Wi, bi, xi_ptr);

    // h = 0
    zero_h<<<(128 * 1024) / 256, 256>>>(h0_ptr);

    // 512 sequential steps (kernel-launch boundary = inter-step dependency)
    const float* src = h0_ptr;
    for (int t = 0; t < 512; t++) {
        float* dst = (t == 511) ? out : ((t & 1) ? h0_ptr : h1_ptr);
        gru_step<<<dim3(32, 4), 256>>>(src, dst, Wh, bh,
                                       xi_ptr + (size_t)t * 128 * 3072);
        src = dst;
    }
}

// round 3
// speedup vs baseline: 2.4514x; 2.4514x over previous
#include <cuda_runtime.h>
#include <math.h>

#define NBLK 128

// ---------------- scratch (__device__ globals; no runtime allocation) ------
__device__ float g_xi[(size_t)512 * 128 * 3072];     // [T][B][3H]
__device__ float g_h[128 * 1024];                    // current hidden state
__device__ float g_cp[4][(size_t)128 * 3072];        // split-K partials
__device__ unsigned g_bar_count;
__device__ volatile unsigned g_bar_sense;

// ---------------- f32x2 packed-FMA helpers ---------------------------------
__device__ __forceinline__ unsigned long long dup2(float x) {
    unsigned long long r;
    asm("mov.b64 %0, {%1, %1};" : "=l"(r) : "f"(x));
    return r;
}
__device__ __forceinline__ void ffma2(unsigned long long& d,
                                      unsigned long long a, unsigned long long b) {
    asm("fma.rn.f32x2 %0, %1, %2, %0;" : "+l"(d) : "l"(a), "l"(b));
}
__device__ __forceinline__ float2 unpack2(unsigned long long v) {
    float2 f;
    asm("mov.b64 {%0, %1}, %2;" : "=f"(f.x), "=f"(f.y) : "l"(v));
    return f;
}

// ---------------- xi = x @ Wi + bi  (M=65536, N=3072, K=512) ---------------
__global__ __launch_bounds__(256) void xi_gemm(
    const float* __restrict__ x, const float* __restrict__ Wi,
    const float* __restrict__ bi, float* __restrict__ xi)
{
    __shared__ float As[16][68];
    __shared__ float Bs[16][64];

    const int n0 = blockIdx.x * 64;
    const int m0 = blockIdx.y * 64;
    const int tx = threadIdx.x & 15;
    const int ty = threadIdx.x >> 4;

    unsigned long long acc[4][2];
#pragma unroll
    for (int i = 0; i < 4; i++) { acc[i][0] = 0ull; acc[i][1] = 0ull; }

    const unsigned bshared =
        (unsigned)__cvta_generic_to_shared(&Bs[0][tx * 4]);

    for (int k0 = 0; k0 < 512; k0 += 16) {
        {
            const int mloc = threadIdx.x >> 2;
            const int kk   = (threadIdx.x & 3) * 4;
            const int m = m0 + mloc;
            const int t = m >> 7;
            const int b = m & 127;
            const float4 v = *reinterpret_cast<const float4*>(
                &x[((size_t)b * 512 + t) * 512 + k0 + kk]);
            As[kk + 0][mloc] = v.x;
            As[kk + 1][mloc] = v.y;
            As[kk + 2][mloc] = v.z;
            As[kk + 3][mloc] = v.w;
        }
        {
            const int kk   = threadIdx.x >> 4;
            const int nloc = (threadIdx.x & 15) * 4;
            *reinterpret_cast<float4*>(&Bs[kk][nloc]) =
                *reinterpret_cast<const float4*>(
                    &Wi[(size_t)(k0 + kk) * 3072 + n0 + nloc]);
        }
        __syncthreads();

#pragma unroll
        for (int kk = 0; kk < 16; kk++) {
            unsigned long long b0, b1;
            asm("ld.shared.v2.u64 {%0, %1}, [%2];"
                : "=l"(b0), "=l"(b1) : "r"(bshared + kk * 256));
            const float4 af = *reinterpret_cast<const float4*>(&As[kk][ty * 4]);
            const unsigned long long a0 = dup2(af.x), a1 = dup2(af.y),
                                     a2 = dup2(af.z), a3 = dup2(af.w);
            ffma2(acc[0][0], a0, b0); ffma2(acc[0][1], a0, b1);
            ffma2(acc[1][0], a1, b0); ffma2(acc[1][1], a1, b1);
            ffma2(acc[2][0], a2, b0); ffma2(acc[2][1], a2, b1);
            ffma2(acc[3][0], a3, b0); ffma2(acc[3][1], a3, b1);
        }
        __syncthreads();
    }

    const int nb = n0 + tx * 4;
    const float4 bv = *reinterpret_cast<const float4*>(&bi[nb]);
#pragma unroll
    for (int i = 0; i < 4; i++) {
        const int m = m0 + ty * 4 + i;
        const float2 c0 = unpack2(acc[i][0]);
        const float2 c1 = unpack2(acc[i][1]);
        float4 o;
        o.x = c0.x + bv.x; o.y = c0.y + bv.y;
        o.z = c1.x + bv.z; o.w = c1.y + bv.w;
        *reinterpret_cast<float4*>(&xi[(size_t)m * 3072 + nb]) = o;
    }
}

// ---------------- init: zero h + reset barrier ------------------------------
__global__ void init_state()
{
    const int idx = blockIdx.x * 256 + threadIdx.x;
    if (idx < 128 * 1024) g_h[idx] = 0.f;
    if (idx == 0) { g_bar_count = 0; g_bar_sense = 0; }
}

// ---------------- grid barrier (sense as monotone counter) ------------------
__device__ __forceinline__ void grid_barrier(unsigned& sense)
{
    __syncthreads();
    if (threadIdx.x == 0) {
        const unsigned s = sense + 1;
        __threadfence();  // make this block's writes visible (L2)
        if (atomicAdd(&g_bar_count, 1u) == gridDim.x - 1) {
            atomicExch(&g_bar_count, 0u);
            __threadfence();
            g_bar_sense = s;
        } else {
            while (g_bar_sense != s) { __nanosleep(64); }
        }
        __threadfence();  // acquire: invalidate L1D (CCTL.IVALL) before reads
        sense = s;
    }
    __syncthreads();
}

// ---------------- persistent GRU recurrence ---------------------------------
// grid = 128 blocks x 256 threads, all co-resident.
// Per step: phase A = h @ Wh split into 384 (tile, k-slice) units, 3/block;
//           phase B = gates on 1024 elems/block, in-place h update.
__global__ __launch_bounds__(256) void gru_persist(
    const float* __restrict__ Wh, const float* __restrict__ bh,
    float* __restrict__ out)
{
    __shared__ float As[16][68];
    __shared__ float Bs[16][64];

    const int tid = threadIdx.x;
    const int bid = blockIdx.x;
    const int tx = tid & 15;
    const int ty = tid >> 4;
    unsigned sense = 0;

    const unsigned bshared =
        (unsigned)__cvta_generic_to_shared(&Bs[0][tx * 4]);

#pragma unroll 1
    for (int t = 0; t < 512; t++) {
        const float* __restrict__ xi_t = g_xi + (size_t)t * 128 * 3072;

        // ---------------- phase A: C_partials = h @ Wh ----------------
#pragma unroll 1
        for (int iu = 0; iu < 3; iu++) {
            const int unit = iu * NBLK + bid;   // 0..383
            const int tile = unit % 96;
            const int kz   = unit / 96;
            const int m0   = (tile & 1) * 64;
            const int n0   = (tile >> 1) * 64;
            const int kbeg = kz * 256;
            float* __restrict__ cpart = g_cp[kz];

            unsigned long long acc[4][2];
#pragma unroll
            for (int i = 0; i < 4; i++) { acc[i][0] = 0ull; acc[i][1] = 0ull; }

#pragma unroll 1
            for (int k0 = kbeg; k0 < kbeg + 256; k0 += 16) {
                {
                    const int mloc = tid >> 2;
                    const int kk   = (tid & 3) * 4;
                    const float4 v = *reinterpret_cast<const float4*>(
                        &g_h[(m0 + mloc) * 1024 + k0 + kk]);
                    As[kk + 0][mloc] = v.x;
                    As[kk + 1][mloc] = v.y;
                    As[kk + 2][mloc] = v.z;
                    As[kk + 3][mloc] = v.w;
                }
                {
                    const int kk   = tid >> 4;
                    const int nloc = (tid & 15) * 4;
                    *reinterpret_cast<float4*>(&Bs[kk][nloc]) =
                        *reinterpret_cast<const float4*>(
                            &Wh[(size_t)(k0 + kk) * 3072 + n0 + nloc]);
                }
                __syncthreads();

#pragma unroll
                for (int kk = 0; kk < 16; kk++) {
                    unsigned long long b0, b1;
                    asm("ld.shared.v2.u64 {%0, %1}, [%2];"
                        : "=l"(b0), "=l"(b1) : "r"(bshared + kk * 256));
                    const float4 af =
                        *reinterpret_cast<const float4*>(&As[kk][ty * 4]);
                    const unsigned long long a0 = dup2(af.x), a1 = dup2(af.y),
                                             a2 = dup2(af.z), a3 = dup2(af.w);
                    ffma2(acc[0][0], a0, b0); ffma2(acc[0][1], a0, b1);
                    ffma2(acc[1][0], a1, b0); ffma2(acc[1][1], a1, b1);
                    ffma2(acc[2][0], a2, b0); ffma2(acc[2][1], a2, b1);
                    ffma2(acc[3][0], a3, b0); ffma2(acc[3][1], a3, b1);
                }
                __syncthreads();
            }

            const int nb = n0 + tx * 4;
#pragma unroll
            for (int i = 0; i < 4; i++) {
                const int m = m0 + ty * 4 + i;
                const float2 c0 = unpack2(acc[i][0]);
                const float2 c1 = unpack2(acc[i][1]);
                float4 o; o.x = c0.x; o.y = c0.y; o.z = c1.x; o.w = c1.y;
                *reinterpret_cast<float4*>(&cpart[(size_t)m * 3072 + nb]) = o;
            }
        }

        grid_barrier(sense);

        // ---------------- phase B: gates, in-place h update ----------------
#pragma unroll
        for (int r = 0; r < 4; r++) {
            const int idx = bid * 1024 + r * 256 + tid;  // = b*1024 + j
            const int b = idx >> 10;
            const int j = idx & 1023;
            const size_t row = (size_t)b * 3072;

            const float hr = g_cp[0][row + j] + g_cp[1][row + j]
                           + g_cp[2][row + j] + g_cp[3][row + j] + bh[j];
            const float hz = g_cp[0][row + 1024 + j] + g_cp[1][row + 1024 + j]
                           + g_cp[2][row + 1024 + j] + g_cp[3][row + 1024 + j]
                           + bh[1024 + j];
            const float hn = g_cp[0][row + 2048 + j] + g_cp[1][row + 2048 + j]
                           + g_cp[2][row + 2048 + j] + g_cp[3][row + 2048 + j]
                           + bh[2048 + j];

            const float ir  = xi_t[row + j];
            const float iz  = xi_t[row + 1024 + j];
            const float inn = xi_t[row + 2048 + j];

            const float rg = 1.f / (1.f + expf(-(ir + hr)));
            const float zg = 1.f / (1.f + expf(-(iz + hz)));
            const float ng = tanhf(inn + rg * hn);

            const float hprev = g_h[idx];
            const float hy = zg * ng + (1.f - zg) * hprev;
            g_h[idx] = hy;
            if (t == 511) out[idx] = hy;
        }

        grid_barrier(sense);
    }
}

// ---------------- launch ----------------------------------------------------
extern "C" void kernel_launch(void* const* d_in, const int* in_sizes, int n_in,
                              void* d_out, int out_size)
{
    const float* x  = (const float*)d_in[0];
    const float* Wi = (const float*)d_in[1];
    const float* bi = (const float*)d_in[2];
    const float* Wh = (const float*)d_in[3];
    const float* bh = (const float*)d_in[4];
    float* out = (float*)d_out;

    float* xi_ptr;
    cudaGetSymbolAddress((void**)&xi_ptr, g_xi);

    // xi = x @ Wi + bi for all timesteps  (one node)
    xi_gemm<<<dim3(3072 / 64, 65536 / 64), 256>>>(x, Wi, bi, xi_ptr);

    // zero h + reset barrier (one node)
    init_state<<<(128 * 1024) / 256, 256>>>();

    // whole 512-step recurrence (one node)
    gru_persist<<<NBLK, 256>>>(Wh, bh, out);
}

// round 5
// speedup vs baseline: 5.3873x; 2.1977x over previous
#include <cuda_runtime.h>
#include <cuda_bf16.h>
#include <math.h>
#include <stdint.h>

#define NC      128       // persistent CTAs; CTA owns hidden slice j0 = bid*8
#define TSTEPS  512

// ---------------- scratch (__device__ globals; no runtime allocation) ------
__device__ float g_xi[(size_t)512 * 128 * 3072];     // [T][B][3H]
__device__ __nv_bfloat16 g_hhi[2][128 * 1024];       // h hi (ping-pong)
__device__ __nv_bfloat16 g_hlo[2][128 * 1024];       // h lo
__device__ unsigned g_bar_count;
__device__ volatile unsigned g_bar_sense;

// ---------------- SMEM layout (dynamic, bytes) -------------------------------
// ws: pre-formatted B fragments: [term2][ks64][gate3][lane32][reg2] u32 = 96KB
// A staging: [buf2][term2][128 rows][72 bf16]  (pad 8 -> 144B row stride)
#define WS_OFF    0
#define WS_BYTES  98304
#define A_OFF     98304
#define A_TERM_SZ 18432          // 128*144
#define SMEM_TOTAL (98304 + 4 * 18432)   // 172032

// ---------------- PTX helpers ------------------------------------------------
__device__ __forceinline__ void mma_bf16(float* c, const uint32_t* a,
                                         uint32_t b0, uint32_t b1) {
    asm volatile(
        "mma.sync.aligned.m16n8k16.row.col.f32.bf16.bf16.f32 "
        "{%0,%1,%2,%3}, {%4,%5,%6,%7}, {%8,%9}, {%0,%1,%2,%3};"
        : "+f"(c[0]), "+f"(c[1]), "+f"(c[2]), "+f"(c[3])
        : "r"(a[0]), "r"(a[1]), "r"(a[2]), "r"(a[3]), "r"(b0), "r"(b1));
}

__device__ __forceinline__ void ldmatrix_x4(uint32_t* a, uint32_t addr) {
    asm volatile(
        "ldmatrix.sync.aligned.m8n8.x4.shared.b16 {%0,%1,%2,%3}, [%4];"
        : "=r"(a[0]), "=r"(a[1]), "=r"(a[2]), "=r"(a[3]) : "r"(addr));
}

__device__ __forceinline__ void cp16(uint32_t dst, const void* src) {
    asm volatile("cp.async.cg.shared.global [%0], [%1], 16;"
                 :: "r"(dst), "l"(src) : "memory");
}

// ---------------- f32x2 packed-FMA helpers (xi_gemm) ------------------------
__device__ __forceinline__ unsigned long long dup2(float x) {
    unsigned long long r;
    asm("mov.b64 %0, {%1, %1};" : "=l"(r) : "f"(x));
    return r;
}
__device__ __forceinline__ void ffma2(unsigned long long& d,
                                      unsigned long long a, unsigned long long b) {
    asm("fma.rn.f32x2 %0, %1, %2, %0;" : "+l"(d) : "l"(a), "l"(b));
}
__device__ __forceinline__ float2 unpack2(unsigned long long v) {
    float2 f;
    asm("mov.b64 {%0, %1}, %2;" : "=f"(f.x), "=f"(f.y) : "l"(v));
    return f;
}

// ---------------- xi = x @ Wi + bi  (M=65536, N=3072, K=512), fp32 ----------
__global__ __launch_bounds__(256) void xi_gemm(
    const float* __restrict__ x, const float* __restrict__ Wi,
    const float* __restrict__ bi, float* __restrict__ xi)
{
    __shared__ float As[16][68];
    __shared__ float Bs[16][64];

    const int n0 = blockIdx.x * 64;
    const int m0 = blockIdx.y * 64;
    const int tx = threadIdx.x & 15;
    const int ty = threadIdx.x >> 4;

    unsigned long long acc[4][2];
#pragma unroll
    for (int i = 0; i < 4; i++) { acc[i][0] = 0ull; acc[i][1] = 0ull; }

    const unsigned bshared = (unsigned)__cvta_generic_to_shared(&Bs[0][tx * 4]);

    for (int k0 = 0; k0 < 512; k0 += 16) {
        {
            const int mloc = threadIdx.x >> 2;
            const int kk   = (threadIdx.x & 3) * 4;
            const int m = m0 + mloc;
            const int t = m >> 7;
            const int b = m & 127;
            const float4 v = *reinterpret_cast<const float4*>(
                &x[((size_t)b * 512 + t) * 512 + k0 + kk]);
            As[kk + 0][mloc] = v.x; As[kk + 1][mloc] = v.y;
            As[kk + 2][mloc] = v.z; As[kk + 3][mloc] = v.w;
        }
        {
            const int kk   = threadIdx.x >> 4;
            const int nloc = (threadIdx.x & 15) * 4;
            *reinterpret_cast<float4*>(&Bs[kk][nloc]) =
                *reinterpret_cast<const float4*>(
                    &Wi[(size_t)(k0 + kk) * 3072 + n0 + nloc]);
        }
        __syncthreads();

#pragma unroll
        for (int kk = 0; kk < 16; kk++) {
            unsigned long long b0, b1;
            asm("ld.shared.v2.u64 {%0, %1}, [%2];"
                : "=l"(b0), "=l"(b1) : "r"(bshared + kk * 256));
            const float4 af = *reinterpret_cast<const float4*>(&As[kk][ty * 4]);
            const unsigned long long a0 = dup2(af.x), a1 = dup2(af.y),
                                     a2 = dup2(af.z), a3 = dup2(af.w);
            ffma2(acc[0][0], a0, b0); ffma2(acc[0][1], a0, b1);
            ffma2(acc[1][0], a1, b0); ffma2(acc[1][1], a1, b1);
            ffma2(acc[2][0], a2, b0); ffma2(acc[2][1], a2, b1);
            ffma2(acc[3][0], a3, b0); ffma2(acc[3][1], a3, b1);
        }
        __syncthreads();
    }

    const int nb = n0 + tx * 4;
    const float4 bv = *reinterpret_cast<const float4*>(&bi[nb]);
#pragma unroll
    for (int i = 0; i < 4; i++) {
        const int m = m0 + ty * 4 + i;
        const float2 c0 = unpack2(acc[i][0]);
        const float2 c1 = unpack2(acc[i][1]);
        float4 o;
        o.x = c0.x + bv.x; o.y = c0.y + bv.y;
        o.z = c1.x + bv.z; o.w = c1.y + bv.w;
        *reinterpret_cast<float4*>(&xi[(size_t)m * 3072 + nb]) = o;
    }
}

// ---------------- init: zero h buffer 0 + reset barrier ---------------------
__global__ void init_state()
{
    const int idx = blockIdx.x * 256 + threadIdx.x;   // < 131072
    const __nv_bfloat16 z = __float2bfloat16(0.f);
    g_hhi[0][idx] = z;
    g_hlo[0][idx] = z;
    if (idx == 0) { g_bar_count = 0; g_bar_sense = 0; }
}

// ---------------- grid barrier ----------------------------------------------
__device__ __forceinline__ void grid_barrier(unsigned& sense)
{
    __syncthreads();
    if (threadIdx.x == 0) {
        const unsigned s = sense + 1;
        __threadfence();
        if (atomicAdd(&g_bar_count, 1u) == gridDim.x - 1) {
            atomicExch(&g_bar_count, 0u);
            __threadfence();
            g_bar_sense = s;
        } else {
            while (g_bar_sense != s) { __nanosleep(32); }
        }
        __threadfence();
        sense = s;
    }
    __syncthreads();
}

// ---------------- persistent mma.sync GRU recurrence -------------------------
// 128 CTAs x 256 threads (8 warps). CTA owns j-slice j0 = bid*8 across all
// 3 gates (N=24). Warp w handles batch rows [w*16, w*16+16).
// Weights live in SMEM as pre-formatted mma B fragments for all 512 steps.
__global__ __launch_bounds__(256, 1)
void gru_mma_persist(const float* __restrict__ Wh, const float* __restrict__ bh,
                     float* __restrict__ out)
{
    extern __shared__ char sm[];
    const uint32_t smem_u32 = (uint32_t)__cvta_generic_to_shared(sm);
    uint32_t* const ws = reinterpret_cast<uint32_t*>(sm + WS_OFF);

    const int tid  = threadIdx.x;
    const int wid  = tid >> 5;
    const int lane = tid & 31;
    const int bid  = blockIdx.x;
    const int j0   = bid * 8;

    // ---- one-time: format Wh slice into mma B fragments (hi & lo terms) ----
    // storage u32 index = ((term*64 + ks)*3 + tt)*64 + l*2 + r
    for (int idx = tid; idx < 24576; idx += 256) {
        const int r    = idx & 1;
        const int l    = (idx >> 1) & 31;
        const int rest = idx >> 6;
        const int tt   = rest % 3;
        const int kst  = rest / 3;
        const int ks   = kst & 63;
        const int term = kst >> 6;
        const int n = tt * 1024 + j0 + (l >> 2);
        const int k = ks * 16 + r * 8 + (l & 3) * 2;

        const float w0 = Wh[(size_t)k * 3072 + n];
        const float w1 = Wh[(size_t)(k + 1) * 3072 + n];
        const __nv_bfloat16 h0 = __float2bfloat16(w0);
        const __nv_bfloat16 h1 = __float2bfloat16(w1);
        __nv_bfloat16 e0, e1;
        if (term == 0) { e0 = h0; e1 = h1; }
        else {
            e0 = __float2bfloat16(w0 - __bfloat162float(h0));
            e1 = __float2bfloat16(w1 - __bfloat162float(h1));
        }
        const uint32_t p = ((uint32_t)__bfloat16_as_ushort(e1) << 16)
                         |  (uint32_t)__bfloat16_as_ushort(e0);
        ws[idx] = p;
    }
    __syncthreads();

    // per-thread fixed output coordinates
    const int b0 = wid * 16 + (lane >> 2);      // batch rows b0, b0+8
    const int jb = j0 + (lane & 3) * 2;         // cols jb, jb+1

    float bhv[3][2];
#pragma unroll
    for (int g = 0; g < 3; g++) {
        bhv[g][0] = bh[g * 1024 + jb];
        bhv[g][1] = bh[g * 1024 + jb + 1];
    }

    float hp[4];   // hprev at (b0,jb),(b0,jb+1),(b0+8,jb),(b0+8,jb+1)
#pragma unroll
    for (int p = 0; p < 4; p++) hp[p] = 0.f;

    unsigned sense = 0;

#pragma unroll 1
    for (int t = 0; t < TSTEPS; t++) {
        const float* __restrict__ xi_t = g_xi + (size_t)t * 128 * 3072;
        const __nv_bfloat16* __restrict__ hs_hi = g_hhi[t & 1];
        const __nv_bfloat16* __restrict__ hs_lo = g_hlo[t & 1];
        __nv_bfloat16* __restrict__ hd_hi = g_hhi[(t + 1) & 1];
        __nv_bfloat16* __restrict__ hd_lo = g_hlo[(t + 1) & 1];

        // xi prefetch into registers (hides DRAM latency behind mainloop)
        float xiv[3][2][2];
#pragma unroll
        for (int g = 0; g < 3; g++)
#pragma unroll
            for (int rr = 0; rr < 2; rr++) {
                const float2 v = *reinterpret_cast<const float2*>(
                    &xi_t[(size_t)(b0 + rr * 8) * 3072 + g * 1024 + jb]);
                xiv[g][rr][0] = v.x; xiv[g][rr][1] = v.y;
            }

        float acc[3][4];
#pragma unroll
        for (int g = 0; g < 3; g++)
#pragma unroll
            for (int p = 0; p < 4; p++) acc[g][p] = 0.f;

        // prologue: stage k-chunk 0 into buf 0
        {
#pragma unroll
            for (int it = 0; it < 4; it++) {
                const int idx = tid + it * 256;
                const int row = idx >> 3, off = idx & 7;
                const uint32_t d = smem_u32 + A_OFF + row * 144 + off * 16;
                cp16(d,             &hs_hi[row * 1024 + off * 8]);
                cp16(d + A_TERM_SZ, &hs_lo[row * 1024 + off * 8]);
            }
            asm volatile("cp.async.commit_group;" ::: "memory");
        }

#pragma unroll 1
        for (int c = 0; c < 16; c++) {
            asm volatile("cp.async.wait_group 0;" ::: "memory");
            __syncthreads();

            if (c < 15) {   // stage chunk c+1 into other buffer
                const int nb = (c + 1) & 1;
                const int kb = (c + 1) * 64;
#pragma unroll
                for (int it = 0; it < 4; it++) {
                    const int idx = tid + it * 256;
                    const int row = idx >> 3, off = idx & 7;
                    const uint32_t d = smem_u32 + A_OFF + nb * 2 * A_TERM_SZ
                                     + row * 144 + off * 16;
                    cp16(d,             &hs_hi[row * 1024 + kb + off * 8]);
                    cp16(d + A_TERM_SZ, &hs_lo[row * 1024 + kb + off * 8]);
                }
                asm volatile("cp.async.commit_group;" ::: "memory");
            }

            // compute chunk c (4 k-steps of 16)
            const uint32_t abase = smem_u32 + A_OFF + (c & 1) * 2 * A_TERM_SZ
                                 + (wid * 16 + (lane & 15)) * 144
                                 + (lane >> 4) * 16;
#pragma unroll
            for (int kk = 0; kk < 4; kk++) {
                uint32_t a_hi[4], a_lo[4];
                ldmatrix_x4(a_hi, abase + kk * 32);
                ldmatrix_x4(a_lo, abase + kk * 32 + A_TERM_SZ);
                const int ks = c * 4 + kk;
#pragma unroll
                for (int tt = 0; tt < 3; tt++) {
                    const uint32_t boff = smem_u32 + WS_OFF
                                        + (uint32_t)((ks * 3 + tt) * 256) + lane * 8;
                    uint32_t bh0, bh1, bl0, bl1;
                    asm("ld.shared.v2.u32 {%0,%1}, [%2];"
                        : "=r"(bh0), "=r"(bh1) : "r"(boff));
                    asm("ld.shared.v2.u32 {%0,%1}, [%2];"
                        : "=r"(bl0), "=r"(bl1) : "r"(boff + 49152u));
                    mma_bf16(acc[tt], a_hi, bh0, bh1);
                    mma_bf16(acc[tt], a_hi, bl0, bl1);
                    mma_bf16(acc[tt], a_lo, bh0, bh1);
                }
            }
        }

        // ---------------- gate epilogue (all in registers) ----------------
#pragma unroll
        for (int rr = 0; rr < 2; rr++) {
            const int b = b0 + rr * 8;
            float hy2[2];
#pragma unroll
            for (int q = 0; q < 2; q++) {
                const int p = rr * 2 + q;
                const float hr = acc[0][p] + bhv[0][q];
                const float hz = acc[1][p] + bhv[1][q];
                const float hn = acc[2][p] + bhv[2][q];
                const float rg = 1.f / (1.f + expf(-(xiv[0][rr][q] + hr)));
                const float zg = 1.f / (1.f + expf(-(xiv[1][rr][q] + hz)));
                const float ng = tanhf(xiv[2][rr][q] + rg * hn);
                const float hy = zg * ng + (1.f - zg) * hp[p];
                hp[p] = hy;
                hy2[q] = hy;
            }
            // write h hi/lo (bf16x2) for next step
            const __nv_bfloat16 e0 = __float2bfloat16(hy2[0]);
            const __nv_bfloat16 e1 = __float2bfloat16(hy2[1]);
            const __nv_bfloat16 l0 = __float2bfloat16(hy2[0] - __bfloat162float(e0));
            const __nv_bfloat16 l1 = __float2bfloat16(hy2[1] - __bfloat162float(e1));
            *reinterpret_cast<uint32_t*>(&hd_hi[b * 1024 + jb]) =
                ((uint32_t)__bfloat16_as_ushort(e1) << 16)
                | (uint32_t)__bfloat16_as_ushort(e0);
            *reinterpret_cast<uint32_t*>(&hd_lo[b * 1024 + jb]) =
                ((uint32_t)__bfloat16_as_ushort(l1) << 16)
                | (uint32_t)__bfloat16_as_ushort(l0);
            if (t == TSTEPS - 1) {
                float2 o; o.x = hy2[0]; o.y = hy2[1];
                *reinterpret_cast<float2*>(&out[b * 1024 + jb]) = o;
            }
        }

        if (t != TSTEPS - 1) grid_barrier(sense);
    }
}

// ---------------- launch ----------------------------------------------------
extern "C" void kernel_launch(void* const* d_in, const int* in_sizes, int n_in,
                              void* d_out, int out_size)
{
    const float* x  = (const float*)d_in[0];
    const float* Wi = (const float*)d_in[1];
    const float* bi = (const float*)d_in[2];
    const float* Wh = (const float*)d_in[3];
    const float* bh = (const float*)d_in[4];
    float* out = (float*)d_out;

    float* xi_ptr;
    cudaGetSymbolAddress((void**)&xi_ptr, g_xi);

    cudaFuncSetAttribute(gru_mma_persist,
                         cudaFuncAttributeMaxDynamicSharedMemorySize, SMEM_TOTAL);

    // xi = x @ Wi + bi for all timesteps
    xi_gemm<<<dim3(48, 1024), 256>>>(x, Wi, bi, xi_ptr);
    // zero h buffer + barrier
    init_state<<<512, 256>>>();
    // whole 512-step recurrence on tensor cores (mma.sync)
    gru_mma_persist<<<NC, 256, SMEM_TOTAL>>>(Wh, bh, out);
}

// round 6
// speedup vs baseline: 7.1344x; 1.3243x over previous
#include <cuda_runtime.h>
#include <cuda_bf16.h>
#include <cuda_fp16.h>
#include <math.h>
#include <stdint.h>

#define NC      128       // persistent CTAs; CTA owns hidden slice j0 = bid*8
#define TSTEPS  512

// ---------------- scratch (__device__ globals; no runtime allocation) ------
__device__ float g_xi[(size_t)512 * 128 * 3072];     // [T][B][3H]
__device__ __half g_xhi[(size_t)128 * 512 * 512];    // x split hi (fp16)
__device__ __half g_xlo[(size_t)128 * 512 * 512];    // x split lo
__device__ __half g_wih[(size_t)512 * 3072];         // Wi fp16
__device__ __nv_bfloat16 g_hhi[2][128 * 1024];       // h hi (ping-pong)
__device__ __nv_bfloat16 g_hlo[2][128 * 1024];       // h lo
__device__ unsigned g_bar_count;
__device__ volatile unsigned g_bar_sense;

// ---------------- recurrence SMEM layout (dynamic, bytes) -------------------
#define WS_OFF    0
#define WS_BYTES  98304
#define A_OFF     98304
#define A_TERM_SZ 18432          // 128*144
#define SMEM_TOTAL (98304 + 4 * 18432)   // 172032

// ---------------- xi mma SMEM layout (bytes) --------------------------------
// A: [buf2][term2][128 rows][72 fp16] ; B: [buf2][64 rows][72 fp16]
#define XA_OFF   0
#define XA_TSZ   18432           // 128*144
#define XA_BUFSZ 36864           // 2 terms
#define XB_OFF   73728
#define XB_BUFSZ 9216            // 64*144
#define SMEM_XI  92160

// ---------------- PTX helpers ------------------------------------------------
__device__ __forceinline__ void mma_bf16(float* c, const uint32_t* a,
                                         uint32_t b0, uint32_t b1) {
    asm volatile(
        "mma.sync.aligned.m16n8k16.row.col.f32.bf16.bf16.f32 "
        "{%0,%1,%2,%3}, {%4,%5,%6,%7}, {%8,%9}, {%0,%1,%2,%3};"
        : "+f"(c[0]), "+f"(c[1]), "+f"(c[2]), "+f"(c[3])
        : "r"(a[0]), "r"(a[1]), "r"(a[2]), "r"(a[3]), "r"(b0), "r"(b1));
}

__device__ __forceinline__ void mma_f16(float* c, const uint32_t* a,
                                        uint32_t b0, uint32_t b1) {
    asm volatile(
        "mma.sync.aligned.m16n8k16.row.col.f32.f16.f16.f32 "
        "{%0,%1,%2,%3}, {%4,%5,%6,%7}, {%8,%9}, {%0,%1,%2,%3};"
        : "+f"(c[0]), "+f"(c[1]), "+f"(c[2]), "+f"(c[3])
        : "r"(a[0]), "r"(a[1]), "r"(a[2]), "r"(a[3]), "r"(b0), "r"(b1));
}

__device__ __forceinline__ void ldmatrix_x4(uint32_t* a, uint32_t addr) {
    asm volatile(
        "ldmatrix.sync.aligned.m8n8.x4.shared.b16 {%0,%1,%2,%3}, [%4];"
        : "=r"(a[0]), "=r"(a[1]), "=r"(a[2]), "=r"(a[3]) : "r"(addr));
}

__device__ __forceinline__ void ldmatrix_x2t(uint32_t& b0, uint32_t& b1,
                                             uint32_t addr) {
    asm volatile(
        "ldmatrix.sync.aligned.m8n8.x2.trans.shared.b16 {%0,%1}, [%2];"
        : "=r"(b0), "=r"(b1) : "r"(addr));
}

__device__ __forceinline__ void cp16(uint32_t dst, const void* src) {
    asm volatile("cp.async.cg.shared.global [%0], [%1], 16;"
                 :: "r"(dst), "l"(src) : "memory");
}

// ---------------- prep: split x into fp16 hi/lo ------------------------------
__global__ __launch_bounds__(256) void split_x(const float* __restrict__ x)
{
    const size_t i = (size_t)blockIdx.x * 256 + threadIdx.x;  // < 33554432
    const float v = x[i];
    const __half hi = __float2half_rn(v);
    g_xhi[i] = hi;
    g_xlo[i] = __float2half_rn(v - __half2float(hi));
}

// ---------------- prep: Wi -> fp16 -------------------------------------------
__global__ __launch_bounds__(256) void split_wi(const float* __restrict__ Wi)
{
    const size_t i = (size_t)blockIdx.x * 256 + threadIdx.x;  // < 1572864
    g_wih[i] = __float2half_rn(Wi[i]);
}

// ---------------- xi = x @ Wi + bi  via mma.sync fp16 2-term -----------------
// grid (48, 512): blockIdx.y = t (M-tile = all 128 batch rows at that t),
// blockIdx.x = 64-wide n-slice. 8 warps as 4(m) x 2(n); warp tile 32m x 32n.
// K = 512 in 8 chunks of 64, cp.async double-buffered.
__global__ __launch_bounds__(256, 2) void xi_mma(
    const float* __restrict__ bi, float* __restrict__ xi)
{
    extern __shared__ char sm[];
    const uint32_t su = (uint32_t)__cvta_generic_to_shared(sm);

    const int tid  = threadIdx.x;
    const int wid  = tid >> 5;
    const int lane = tid & 31;
    const int t    = blockIdx.y;
    const int n0   = blockIdx.x * 64;
    const int wm   = wid >> 1;            // 0..3 (m)
    const int wn   = wid & 1;             // 0..1 (n)

    float acc[2][4][4];
#pragma unroll
    for (int i = 0; i < 2; i++)
#pragma unroll
        for (int j = 0; j < 4; j++)
#pragma unroll
            for (int p = 0; p < 4; p++) acc[i][j][p] = 0.f;

    // stage chunk 0
    {
        const uint32_t ab = su + XA_OFF;
#pragma unroll
        for (int it = 0; it < 8; it++) {
            const int idx = tid + it * 256;          // 0..2047
            const int term = idx >> 10;
            const int r = (idx >> 3) & 127;
            const int off = idx & 7;
            const __half* src = term ? g_xlo : g_xhi;
            cp16(ab + term * XA_TSZ + r * 144 + off * 16,
                 &src[((size_t)r * 512 + t) * 512 + off * 8]);
        }
#pragma unroll
        for (int it = 0; it < 2; it++) {
            const int idx = tid + it * 256;          // 0..511
            const int r = idx >> 3, off = idx & 7;
            cp16(su + XB_OFF + r * 144 + off * 16,
                 &g_wih[(size_t)r * 3072 + n0 + off * 8]);
        }
        asm volatile("cp.async.commit_group;" ::: "memory");
    }

#pragma unroll 1
    for (int c = 0; c < 8; c++) {
        asm volatile("cp.async.wait_group 0;" ::: "memory");
        __syncthreads();

        if (c < 7) {
            const int nb = (c + 1) & 1;
            const int kb = (c + 1) * 64;
            const uint32_t ab = su + XA_OFF + nb * XA_BUFSZ;
#pragma unroll
            for (int it = 0; it < 8; it++) {
                const int idx = tid + it * 256;
                const int term = idx >> 10;
                const int r = (idx >> 3) & 127;
                const int off = idx & 7;
                const __half* src = term ? g_xlo : g_xhi;
                cp16(ab + term * XA_TSZ + r * 144 + off * 16,
                     &src[((size_t)r * 512 + t) * 512 + kb + off * 8]);
            }
#pragma unroll
            for (int it = 0; it < 2; it++) {
                const int idx = tid + it * 256;
                const int r = idx >> 3, off = idx & 7;
                cp16(su + XB_OFF + nb * XB_BUFSZ + r * 144 + off * 16,
                     &g_wih[(size_t)(kb + r) * 3072 + n0 + off * 8]);
            }
            asm volatile("cp.async.commit_group;" ::: "memory");
        }

        const uint32_t abuf = su + XA_OFF + (c & 1) * XA_BUFSZ;
        const uint32_t bbuf = su + XB_OFF + (c & 1) * XB_BUFSZ;
#pragma unroll
        for (int kk = 0; kk < 4; kk++) {
            uint32_t a_hi[2][4], a_lo[2][4];
#pragma unroll
            for (int tile = 0; tile < 2; tile++) {
                const uint32_t aaddr = abuf
                    + (wm * 32 + tile * 16 + (lane & 15)) * 144
                    + (lane >> 4) * 16 + kk * 32;
                ldmatrix_x4(a_hi[tile], aaddr);
                ldmatrix_x4(a_lo[tile], aaddr + XA_TSZ);
            }
            uint32_t bf[4][2];
#pragma unroll
            for (int nt = 0; nt < 4; nt++) {
                const uint32_t baddr = bbuf
                    + (kk * 16 + (lane & 15)) * 144
                    + (wn * 32 + nt * 8) * 2;
                ldmatrix_x2t(bf[nt][0], bf[nt][1], baddr);
            }
#pragma unroll
            for (int tile = 0; tile < 2; tile++)
#pragma unroll
                for (int nt = 0; nt < 4; nt++) {
                    mma_f16(acc[tile][nt], a_hi[tile], bf[nt][0], bf[nt][1]);
                    mma_f16(acc[tile][nt], a_lo[tile], bf[nt][0], bf[nt][1]);
                }
        }
    }

    // epilogue: xi[t][b][n] = acc + bi[n]
    const int grp = lane >> 2;
    const int nlo = (lane & 3) * 2;
#pragma unroll
    for (int nt = 0; nt < 4; nt++) {
        const int n = n0 + wn * 32 + nt * 8 + nlo;
        const float2 bv = *reinterpret_cast<const float2*>(&bi[n]);
#pragma unroll
        for (int tile = 0; tile < 2; tile++) {
#pragma unroll
            for (int half = 0; half < 2; half++) {
                const int b = wm * 32 + tile * 16 + grp + half * 8;
                float2 o;
                o.x = acc[tile][nt][half * 2 + 0] + bv.x;
                o.y = acc[tile][nt][half * 2 + 1] + bv.y;
                *reinterpret_cast<float2*>(
                    &xi[((size_t)t * 128 + b) * 3072 + n]) = o;
            }
        }
    }
}

// ---------------- init: zero h buffer 0 + reset barrier ---------------------
__global__ void init_state()
{
    const int idx = blockIdx.x * 256 + threadIdx.x;   // < 131072
    const __nv_bfloat16 z = __float2bfloat16(0.f);
    g_hhi[0][idx] = z;
    g_hlo[0][idx] = z;
    if (idx == 0) { g_bar_count = 0; g_bar_sense = 0; }
}

// ---------------- grid barrier ----------------------------------------------
__device__ __forceinline__ void grid_barrier(unsigned& sense)
{
    __syncthreads();
    if (threadIdx.x == 0) {
        const unsigned s = sense + 1;
        __threadfence();
        if (atomicAdd(&g_bar_count, 1u) == gridDim.x - 1) {
            atomicExch(&g_bar_count, 0u);
            __threadfence();
            g_bar_sense = s;
        } else {
            while (g_bar_sense != s) { __nanosleep(32); }
        }
        __threadfence();
        sense = s;
    }
    __syncthreads();
}

// ---------------- persistent mma.sync GRU recurrence -------------------------
// (unchanged from round-5 passing kernel)
__global__ __launch_bounds__(256, 1)
void gru_mma_persist(const float* __restrict__ Wh, const float* __restrict__ bh,
                     float* __restrict__ out)
{
    extern __shared__ char sm[];
    const uint32_t smem_u32 = (uint32_t)__cvta_generic_to_shared(sm);
    uint32_t* const ws = reinterpret_cast<uint32_t*>(sm + WS_OFF);

    const int tid  = threadIdx.x;
    const int wid  = tid >> 5;
    const int lane = tid & 31;
    const int bid  = blockIdx.x;
    const int j0   = bid * 8;

    // one-time: format Wh slice into mma B fragments (hi & lo terms)
    for (int idx = tid; idx < 24576; idx += 256) {
        const int r    = idx & 1;
        const int l    = (idx >> 1) & 31;
        const int rest = idx >> 6;
        const int tt   = rest % 3;
        const int kst  = rest / 3;
        const int ks   = kst & 63;
        const int term = kst >> 6;
        const int n = tt * 1024 + j0 + (l >> 2);
        const int k = ks * 16 + r * 8 + (l & 3) * 2;

        const float w0 = Wh[(size_t)k * 3072 + n];
        const float w1 = Wh[(size_t)(k + 1) * 3072 + n];
        const __nv_bfloat16 h0 = __float2bfloat16(w0);
        const __nv_bfloat16 h1 = __float2bfloat16(w1);
        __nv_bfloat16 e0, e1;
        if (term == 0) { e0 = h0; e1 = h1; }
        else {
            e0 = __float2bfloat16(w0 - __bfloat162float(h0));
            e1 = __float2bfloat16(w1 - __bfloat162float(h1));
        }
        ws[idx] = ((uint32_t)__bfloat16_as_ushort(e1) << 16)
                |  (uint32_t)__bfloat16_as_ushort(e0);
    }
    __syncthreads();

    const int b0 = wid * 16 + (lane >> 2);
    const int jb = j0 + (lane & 3) * 2;

    float bhv[3][2];
#pragma unroll
    for (int g = 0; g < 3; g++) {
        bhv[g][0] = bh[g * 1024 + jb];
        bhv[g][1] = bh[g * 1024 + jb + 1];
    }

    float hp[4];
#pragma unroll
    for (int p = 0; p < 4; p++) hp[p] = 0.f;

    unsigned sense = 0;

#pragma unroll 1
    for (int t = 0; t < TSTEPS; t++) {
        const float* __restrict__ xi_t = g_xi + (size_t)t * 128 * 3072;
        const __nv_bfloat16* __restrict__ hs_hi = g_hhi[t & 1];
        const __nv_bfloat16* __restrict__ hs_lo = g_hlo[t & 1];
        __nv_bfloat16* __restrict__ hd_hi = g_hhi[(t + 1) & 1];
        __nv_bfloat16* __restrict__ hd_lo = g_hlo[(t + 1) & 1];

        float xiv[3][2][2];
#pragma unroll
        for (int g = 0; g < 3; g++)
#pragma unroll
            for (int rr = 0; rr < 2; rr++) {
                const float2 v = *reinterpret_cast<const float2*>(
                    &xi_t[(size_t)(b0 + rr * 8) * 3072 + g * 1024 + jb]);
                xiv[g][rr][0] = v.x; xiv[g][rr][1] = v.y;
            }

        float acc[3][4];
#pragma unroll
        for (int g = 0; g < 3; g++)
#pragma unroll
            for (int p = 0; p < 4; p++) acc[g][p] = 0.f;

        {
#pragma unroll
            for (int it = 0; it < 4; it++) {
                const int idx = tid + it * 256;
                const int row = idx >> 3, off = idx & 7;
                const uint32_t d = smem_u32 + A_OFF + row * 144 + off * 16;
                cp16(d,             &hs_hi[row * 1024 + off * 8]);
                cp16(d + A_TERM_SZ, &hs_lo[row * 1024 + off * 8]);
            }
            asm volatile("cp.async.commit_group;" ::: "memory");
        }

#pragma unroll 1
        for (int c = 0; c < 16; c++) {
            asm volatile("cp.async.wait_group 0;" ::: "memory");
            __syncthreads();

            if (c < 15) {
                const int nb = (c + 1) & 1;
                const int kb = (c + 1) * 64;
#pragma unroll
                for (int it = 0; it < 4; it++) {
                    const int idx = tid + it * 256;
                    const int row = idx >> 3, off = idx & 7;
                    const uint32_t d = smem_u32 + A_OFF + nb * 2 * A_TERM_SZ
                                     + row * 144 + off * 16;
                    cp16(d,             &hs_hi[row * 1024 + kb + off * 8]);
                    cp16(d + A_TERM_SZ, &hs_lo[row * 1024 + kb + off * 8]);
                }
                asm volatile("cp.async.commit_group;" ::: "memory");
            }

            const uint32_t abase = smem_u32 + A_OFF + (c & 1) * 2 * A_TERM_SZ
                                 + (wid * 16 + (lane & 15)) * 144
                                 + (lane >> 4) * 16;
#pragma unroll
            for (int kk = 0; kk < 4; kk++) {
                uint32_t a_hi[4], a_lo[4];
                ldmatrix_x4(a_hi, abase + kk * 32);
                ldmatrix_x4(a_lo, abase + kk * 32 + A_TERM_SZ);
                const int ks = c * 4 + kk;
#pragma unroll
                for (int tt = 0; tt < 3; tt++) {
                    const uint32_t boff = smem_u32 + WS_OFF
                                        + (uint32_t)((ks * 3 + tt) * 256) + lane * 8;
                    uint32_t bh0, bh1, bl0, bl1;
                    asm("ld.shared.v2.u32 {%0,%1}, [%2];"
                        : "=r"(bh0), "=r"(bh1) : "r"(boff));
                    asm("ld.shared.v2.u32 {%0,%1}, [%2];"
                        : "=r"(bl0), "=r"(bl1) : "r"(boff + 49152u));
                    mma_bf16(acc[tt], a_hi, bh0, bh1);
                    mma_bf16(acc[tt], a_hi, bl0, bl1);
                    mma_bf16(acc[tt], a_lo, bh0, bh1);
                }
            }
        }

#pragma unroll
        for (int rr = 0; rr < 2; rr++) {
            const int b = b0 + rr * 8;
            float hy2[2];
#pragma unroll
            for (int q = 0; q < 2; q++) {
                const int p = rr * 2 + q;
                const float hr = acc[0][p] + bhv[0][q];
                const float hz = acc[1][p] + bhv[1][q];
                const float hn = acc[2][p] + bhv[2][q];
                const float rg = 1.f / (1.f + expf(-(xiv[0][rr][q] + hr)));
                const float zg = 1.f / (1.f + expf(-(xiv[1][rr][q] + hz)));
                const float ng = tanhf(xiv[2][rr][q] + rg * hn);
                const float hy = zg * ng + (1.f - zg) * hp[p];
                hp[p] = hy;
                hy2[q] = hy;
            }
            const __nv_bfloat16 e0 = __float2bfloat16(hy2[0]);
            const __nv_bfloat16 e1 = __float2bfloat16(hy2[1]);
            const __nv_bfloat16 l0 = __float2bfloat16(hy2[0] - __bfloat162float(e0));
            const __nv_bfloat16 l1 = __float2bfloat16(hy2[1] - __bfloat162float(e1));
            *reinterpret_cast<uint32_t*>(&hd_hi[b * 1024 + jb]) =
                ((uint32_t)__bfloat16_as_ushort(e1) << 16)
                | (uint32_t)__bfloat16_as_ushort(e0);
            *reinterpret_cast<uint32_t*>(&hd_lo[b * 1024 + jb]) =
                ((uint32_t)__bfloat16_as_ushort(l1) << 16)
                | (uint32_t)__bfloat16_as_ushort(l0);
            if (t == TSTEPS - 1) {
                float2 o; o.x = hy2[0]; o.y = hy2[1];
                *reinterpret_cast<float2*>(&out[b * 1024 + jb]) = o;
            }
        }

        if (t != TSTEPS - 1) grid_barrier(sense);
    }
}

// ---------------- launch ----------------------------------------------------
extern "C" void kernel_launch(void* const* d_in, const int* in_sizes, int n_in,
                              void* d_out, int out_size)
{
    const float* x  = (const float*)d_in[0];
    const float* Wi = (const float*)d_in[1];
    const float* bi = (const float*)d_in[2];
    const float* Wh = (const float*)d_in[3];
    const float* bh = (const float*)d_in[4];
    float* out = (float*)d_out;

    float* xi_ptr;
    cudaGetSymbolAddress((void**)&xi_ptr, g_xi);

    cudaFuncSetAttribute(gru_mma_persist,
                         cudaFuncAttributeMaxDynamicSharedMemorySize, SMEM_TOTAL);
    cudaFuncSetAttribute(xi_mma,
                         cudaFuncAttributeMaxDynamicSharedMemorySize, SMEM_XI);

    // prep: fp16 splits
    split_x<<<131072, 256>>>(x);
    split_wi<<<6144, 256>>>(Wi);
    // xi = x @ Wi + bi on tensor cores (fp16 2-term)
    xi_mma<<<dim3(48, 512), 256, SMEM_XI>>>(bi, xi_ptr);
    // zero h buffer + barrier
    init_state<<<512, 256>>>();
    // whole 512-step recurrence on tensor cores (bf16 3-term)
    gru_mma_persist<<<NC, 256, SMEM_TOTAL>>>(Wh, bh, out);
}

// round 7
// speedup vs baseline: 10.7734x; 1.5101x over previous
#include <cuda_runtime.h>
#include <cuda_bf16.h>
#include <cuda_fp16.h>
#include <math.h>
#include <stdint.h>

#define NC      128       // persistent CTAs; CTA owns hidden slice j0 = bid*8
#define TSTEPS  512

// ---------------- scratch (__device__ globals; no runtime allocation) ------
__device__ float g_xi[(size_t)512 * 128 * 3072];     // [T][B][3H]
__device__ __half g_xhi[(size_t)128 * 512 * 512];    // x split hi (fp16)
__device__ __half g_xlo[(size_t)128 * 512 * 512];    // x split lo
__device__ __half g_wih[(size_t)512 * 3072];         // Wi fp16
__device__ __half g_hf[2][128 * 1024];               // h fp16 (ping-pong)
__device__ unsigned g_bar_count;
__device__ volatile unsigned g_bar_sense;

// ---------------- recurrence SMEM layout (dynamic, bytes) -------------------
// ws: W fragments fp16: [term2][ks64][gate3][lane32][reg2] u32 = 96KB
// A staging: per-warp private, 3 bufs x (16 rows x 272B) = 13056 B/warp
#define WS_OFF     0
#define WS_TERMSZ  49152
#define A_OFF      98304
#define A_BUF_SZ   4352          // 16 rows * 272B
#define A_WARP_SZ  13056         // 3 bufs
#define SMEM_TOTAL (98304 + 8 * 13056)   // 202752

// ---------------- xi mma SMEM layout (bytes) --------------------------------
#define XA_OFF   0
#define XA_TSZ   18432           // 128*144
#define XA_BUFSZ 36864           // 2 terms
#define XB_OFF   73728
#define XB_BUFSZ 9216            // 64*144
#define SMEM_XI  92160

// ---------------- PTX helpers ------------------------------------------------
__device__ __forceinline__ void mma_f16(float* c, const uint32_t* a,
                                        uint32_t b0, uint32_t b1) {
    asm volatile(
        "mma.sync.aligned.m16n8k16.row.col.f32.f16.f16.f32 "
        "{%0,%1,%2,%3}, {%4,%5,%6,%7}, {%8,%9}, {%0,%1,%2,%3};"
        : "+f"(c[0]), "+f"(c[1]), "+f"(c[2]), "+f"(c[3])
        : "r"(a[0]), "r"(a[1]), "r"(a[2]), "r"(a[3]), "r"(b0), "r"(b1));
}

__device__ __forceinline__ void ldmatrix_x4(uint32_t* a, uint32_t addr) {
    asm volatile(
        "ldmatrix.sync.aligned.m8n8.x4.shared.b16 {%0,%1,%2,%3}, [%4];"
        : "=r"(a[0]), "=r"(a[1]), "=r"(a[2]), "=r"(a[3]) : "r"(addr));
}

__device__ __forceinline__ void ldmatrix_x2t(uint32_t& b0, uint32_t& b1,
                                             uint32_t addr) {
    asm volatile(
        "ldmatrix.sync.aligned.m8n8.x2.trans.shared.b16 {%0,%1}, [%2];"
        : "=r"(b0), "=r"(b1) : "r"(addr));
}

__device__ __forceinline__ void cp16(uint32_t dst, const void* src) {
    asm volatile("cp.async.cg.shared.global [%0], [%1], 16;"
                 :: "r"(dst), "l"(src) : "memory");
}

// ---------------- prep: split x into fp16 hi/lo ------------------------------
__global__ __launch_bounds__(256) void split_x(const float* __restrict__ x)
{
    const size_t i = (size_t)blockIdx.x * 256 + threadIdx.x;
    const float v = x[i];
    const __half hi = __float2half_rn(v);
    g_xhi[i] = hi;
    g_xlo[i] = __float2half_rn(v - __half2float(hi));
}

// ---------------- prep: Wi -> fp16 -------------------------------------------
__global__ __launch_bounds__(256) void split_wi(const float* __restrict__ Wi)
{
    const size_t i = (size_t)blockIdx.x * 256 + threadIdx.x;
    g_wih[i] = __float2half_rn(Wi[i]);
}

// ---------------- xi = x @ Wi + bi  via mma.sync fp16 2-term -----------------
// (unchanged from validated round-6 kernel)
__global__ __launch_bounds__(256, 2) void xi_mma(
    const float* __restrict__ bi, float* __restrict__ xi)
{
    extern __shared__ char sm[];
    const uint32_t su = (uint32_t)__cvta_generic_to_shared(sm);

    const int tid  = threadIdx.x;
    const int wid  = tid >> 5;
    const int lane = tid & 31;
    const int t    = blockIdx.y;
    const int n0   = blockIdx.x * 64;
    const int wm   = wid >> 1;
    const int wn   = wid & 1;

    float acc[2][4][4];
#pragma unroll
    for (int i = 0; i < 2; i++)
#pragma unroll
        for (int j = 0; j < 4; j++)
#pragma unroll
            for (int p = 0; p < 4; p++) acc[i][j][p] = 0.f;

    {
        const uint32_t ab = su + XA_OFF;
#pragma unroll
        for (int it = 0; it < 8; it++) {
            const int idx = tid + it * 256;
            const int term = idx >> 10;
            const int r = (idx >> 3) & 127;
            const int off = idx & 7;
            const __half* src = term ? g_xlo : g_xhi;
            cp16(ab + term * XA_TSZ + r * 144 + off * 16,
                 &src[((size_t)r * 512 + t) * 512 + off * 8]);
        }
#pragma unroll
        for (int it = 0; it < 2; it++) {
            const int idx = tid + it * 256;
            const int r = idx >> 3, off = idx & 7;
            cp16(su + XB_OFF + r * 144 + off * 16,
                 &g_wih[(size_t)r * 3072 + n0 + off * 8]);
        }
        asm volatile("cp.async.commit_group;" ::: "memory");
    }

#pragma unroll 1
    for (int c = 0; c < 8; c++) {
        asm volatile("cp.async.wait_group 0;" ::: "memory");
        __syncthreads();

        if (c < 7) {
            const int nb = (c + 1) & 1;
            const int kb = (c + 1) * 64;
            const uint32_t ab = su + XA_OFF + nb * XA_BUFSZ;
#pragma unroll
            for (int it = 0; it < 8; it++) {
                const int idx = tid + it * 256;
                const int term = idx >> 10;
                const int r = (idx >> 3) & 127;
                const int off = idx & 7;
                const __half* src = term ? g_xlo : g_xhi;
                cp16(ab + term * XA_TSZ + r * 144 + off * 16,
                     &src[((size_t)r * 512 + t) * 512 + kb + off * 8]);
            }
#pragma unroll
            for (int it = 0; it < 2; it++) {
                const int idx = tid + it * 256;
                const int r = idx >> 3, off = idx & 7;
                cp16(su + XB_OFF + nb * XB_BUFSZ + r * 144 + off * 16,
                     &g_wih[(size_t)(kb + r) * 3072 + n0 + off * 8]);
            }
            asm volatile("cp.async.commit_group;" ::: "memory");
        }

        const uint32_t abuf = su + XA_OFF + (c & 1) * XA_BUFSZ;
        const uint32_t bbuf = su + XB_OFF + (c & 1) * XB_BUFSZ;
#pragma unroll
        for (int kk = 0; kk < 4; kk++) {
            uint32_t a_hi[2][4], a_lo[2][4];
#pragma unroll
            for (int tile = 0; tile < 2; tile++) {
                const uint32_t aaddr = abuf
                    + (wm * 32 + tile * 16 + (lane & 15)) * 144
                    + (lane >> 4) * 16 + kk * 32;
                ldmatrix_x4(a_hi[tile], aaddr);
                ldmatrix_x4(a_lo[tile], aaddr + XA_TSZ);
            }
            uint32_t bf[4][2];
#pragma unroll
            for (int nt = 0; nt < 4; nt++) {
                const uint32_t baddr = bbuf
                    + (kk * 16 + (lane & 15)) * 144
                    + (wn * 32 + nt * 8) * 2;
                ldmatrix_x2t(bf[nt][0], bf[nt][1], baddr);
            }
#pragma unroll
            for (int tile = 0; tile < 2; tile++)
#pragma unroll
                for (int nt = 0; nt < 4; nt++) {
                    mma_f16(acc[tile][nt], a_hi[tile], bf[nt][0], bf[nt][1]);
                    mma_f16(acc[tile][nt], a_lo[tile], bf[nt][0], bf[nt][1]);
                }
        }
    }

    const int grp = lane >> 2;
    const int nlo = (lane & 3) * 2;
#pragma unroll
    for (int nt = 0; nt < 4; nt++) {
        const int n = n0 + wn * 32 + nt * 8 + nlo;
        const float2 bv = *reinterpret_cast<const float2*>(&bi[n]);
#pragma unroll
        for (int tile = 0; tile < 2; tile++) {
#pragma unroll
            for (int half = 0; half < 2; half++) {
                const int b = wm * 32 + tile * 16 + grp + half * 8;
                float2 o;
                o.x = acc[tile][nt][half * 2 + 0] + bv.x;
                o.y = acc[tile][nt][half * 2 + 1] + bv.y;
                *reinterpret_cast<float2*>(
                    &xi[((size_t)t * 128 + b) * 3072 + n]) = o;
            }
        }
    }
}

// ---------------- init: zero h buffer 0 + reset barrier ---------------------
__global__ void init_state()
{
    const int idx = blockIdx.x * 256 + threadIdx.x;   // < 131072
    g_hf[0][idx] = __float2half(0.f);
    if (idx == 0) { g_bar_count = 0; g_bar_sense = 0; }
}

// ---------------- grid barrier ----------------------------------------------
__device__ __forceinline__ void grid_barrier(unsigned& sense)
{
    __syncthreads();
    if (threadIdx.x == 0) {
        const unsigned s = sense + 1;
        __threadfence();
        if (atomicAdd(&g_bar_count, 1u) == gridDim.x - 1) {
            atomicExch(&g_bar_count, 0u);
            __threadfence();
            g_bar_sense = s;
        } else {
            while (g_bar_sense != s) { __nanosleep(32); }
        }
        __threadfence();
        sense = s;
    }
    __syncthreads();
}

// ---------------- persistent mma.sync GRU recurrence (fp16 2-term) ----------
// 128 CTAs x 256 threads (8 warps). CTA owns j-slice j0 = bid*8 (3 gates,
// N=24). Warp w owns batch rows [w*16, w*16+16) -> A staging is warp-private
// (cp.async 3-stage, __syncwarp only; zero block syncs in the mainloop).
// W fragments (fp16 hi+lo) formatted once into SMEM; h stored as single fp16.
__global__ __launch_bounds__(256, 1)
void gru_mma_persist(const float* __restrict__ Wh, const float* __restrict__ bh,
                     float* __restrict__ out)
{
    extern __shared__ char sm[];
    const uint32_t smem_u32 = (uint32_t)__cvta_generic_to_shared(sm);
    uint32_t* const ws = reinterpret_cast<uint32_t*>(sm + WS_OFF);

    const int tid  = threadIdx.x;
    const int wid  = tid >> 5;
    const int lane = tid & 31;
    const int bid  = blockIdx.x;
    const int j0   = bid * 8;

    // one-time: format Wh slice into fp16 mma B fragments (hi & lo terms)
    for (int idx = tid; idx < 24576; idx += 256) {
        const int r    = idx & 1;
        const int l    = (idx >> 1) & 31;
        const int rest = idx >> 6;
        const int tt   = rest % 3;
        const int kst  = rest / 3;
        const int ks   = kst & 63;
        const int term = kst >> 6;
        const int n = tt * 1024 + j0 + (l >> 2);
        const int k = ks * 16 + r * 8 + (l & 3) * 2;

        const float w0 = Wh[(size_t)k * 3072 + n];
        const float w1 = Wh[(size_t)(k + 1) * 3072 + n];
        const __half h0 = __float2half_rn(w0);
        const __half h1 = __float2half_rn(w1);
        __half e0, e1;
        if (term == 0) { e0 = h0; e1 = h1; }
        else {
            e0 = __float2half_rn(w0 - __half2float(h0));
            e1 = __float2half_rn(w1 - __half2float(h1));
        }
        ws[idx] = ((uint32_t)__half_as_ushort(e1) << 16)
                |  (uint32_t)__half_as_ushort(e0);
    }
    __syncthreads();

    const int b0 = wid * 16 + (lane >> 2);
    const int jb = j0 + (lane & 3) * 2;

    float bhv[3][2];
#pragma unroll
    for (int g = 0; g < 3; g++) {
        bhv[g][0] = bh[g * 1024 + jb];
        bhv[g][1] = bh[g * 1024 + jb + 1];
    }

    float hp[4];
#pragma unroll
    for (int p = 0; p < 4; p++) hp[p] = 0.f;

    // warp-private A staging base
    const uint32_t awarp = smem_u32 + A_OFF + wid * A_WARP_SZ;
    const int arow = wid * 16;    // this warp's first batch row

    unsigned sense = 0;

#pragma unroll 1
    for (int t = 0; t < TSTEPS; t++) {
        const float* __restrict__ xi_t = g_xi + (size_t)t * 128 * 3072;
        const __half* __restrict__ hs = g_hf[t & 1];
        __half* __restrict__ hd = g_hf[(t + 1) & 1];

        // xi prefetch into registers (overlaps with staging/mma)
        float xiv[3][2][2];
#pragma unroll
        for (int g = 0; g < 3; g++)
#pragma unroll
            for (int rr = 0; rr < 2; rr++) {
                const float2 v = *reinterpret_cast<const float2*>(
                    &xi_t[(size_t)(b0 + rr * 8) * 3072 + g * 1024 + jb]);
                xiv[g][rr][0] = v.x; xiv[g][rr][1] = v.y;
            }

        float acc[3][4];
#pragma unroll
        for (int g = 0; g < 3; g++)
#pragma unroll
            for (int p = 0; p < 4; p++) acc[g][p] = 0.f;

        // prologue: stage chunks 0 and 1 (k-chunk = 128)
#pragma unroll
        for (int pc = 0; pc < 2; pc++) {
            const uint32_t ab = awarp + pc * A_BUF_SZ;
#pragma unroll
            for (int it = 0; it < 8; it++) {
                const int idx = lane + it * 32;          // 0..255
                const int row = idx >> 4, off = idx & 15;
                cp16(ab + row * 272 + off * 16,
                     &hs[(arow + row) * 1024 + pc * 128 + off * 8]);
            }
            asm volatile("cp.async.commit_group;" ::: "memory");
        }

#pragma unroll 1
        for (int c = 0; c < 8; c++) {
            if (c < 6)
                asm volatile("cp.async.wait_group 1;" ::: "memory");
            else
                asm volatile("cp.async.wait_group 0;" ::: "memory");
            __syncwarp();

            const uint32_t abuf = awarp + (c % 3) * A_BUF_SZ;
#pragma unroll
            for (int kk = 0; kk < 8; kk++) {
                uint32_t a[4];
                ldmatrix_x4(a, abuf + (lane & 15) * 272
                               + (lane >> 4) * 16 + kk * 32);
                const int ks = c * 8 + kk;
#pragma unroll
                for (int tt = 0; tt < 3; tt++) {
                    const uint32_t boff = smem_u32 + WS_OFF
                                        + (uint32_t)((ks * 3 + tt) * 256) + lane * 8;
                    uint32_t bh0, bh1, bl0, bl1;
                    asm("ld.shared.v2.u32 {%0,%1}, [%2];"
                        : "=r"(bh0), "=r"(bh1) : "r"(boff));
                    asm("ld.shared.v2.u32 {%0,%1}, [%2];"
                        : "=r"(bl0), "=r"(bl1) : "r"(boff + WS_TERMSZ));
                    mma_f16(acc[tt], a, bh0, bh1);
                    mma_f16(acc[tt], a, bl0, bl1);
                }
            }

            if (c < 6) {   // stage chunk c+2
                const uint32_t ab = awarp + ((c + 2) % 3) * A_BUF_SZ;
                const int kb = (c + 2) * 128;
#pragma unroll
                for (int it = 0; it < 8; it++) {
                    const int idx = lane + it * 32;
                    const int row = idx >> 4, off = idx & 15;
                    cp16(ab + row * 272 + off * 16,
                         &hs[(arow + row) * 1024 + kb + off * 8]);
                }
                asm volatile("cp.async.commit_group;" ::: "memory");
            }
        }

        // ---------------- gate epilogue (registers only) ----------------
#pragma unroll
        for (int rr = 0; rr < 2; rr++) {
            const int b = b0 + rr * 8;
            float hy2[2];
#pragma unroll
            for (int q = 0; q < 2; q++) {
                const int p = rr * 2 + q;
                const float hr = acc[0][p] + bhv[0][q];
                const float hz = acc[1][p] + bhv[1][q];
                const float hn = acc[2][p] + bhv[2][q];
                const float rg = 1.f / (1.f + expf(-(xiv[0][rr][q] + hr)));
                const float zg = 1.f / (1.f + expf(-(xiv[1][rr][q] + hz)));
                const float ng = tanhf(xiv[2][rr][q] + rg * hn);
                const float hy = zg * ng + (1.f - zg) * hp[p];
                hp[p] = hy;
                hy2[q] = hy;
            }
            const __half e0 = __float2half_rn(hy2[0]);
            const __half e1 = __float2half_rn(hy2[1]);
            *reinterpret_cast<uint32_t*>(&hd[b * 1024 + jb]) =
                ((uint32_t)__half_as_ushort(e1) << 16)
                | (uint32_t)__half_as_ushort(e0);
            if (t == TSTEPS - 1) {
                float2 o; o.x = hy2[0]; o.y = hy2[1];
                *reinterpret_cast<float2*>(&out[b * 1024 + jb]) = o;
            }
        }

        if (t != TSTEPS - 1) grid_barrier(sense);
    }
}

// ---------------- launch ----------------------------------------------------
extern "C" void kernel_launch(void* const* d_in, const int* in_sizes, int n_in,
                              void* d_out, int out_size)
{
    const float* x  = (const float*)d_in[0];
    const float* Wi = (const float*)d_in[1];
    const float* bi = (const float*)d_in[2];
    const float* Wh = (const float*)d_in[3];
    const float* bh = (const float*)d_in[4];
    float* out = (float*)d_out;

    float* xi_ptr;
    cudaGetSymbolAddress((void**)&xi_ptr, g_xi);

    cudaFuncSetAttribute(gru_mma_persist,
                         cudaFuncAttributeMaxDynamicSharedMemorySize, SMEM_TOTAL);
    cudaFuncSetAttribute(xi_mma,
                         cudaFuncAttributeMaxDynamicSharedMemorySize, SMEM_XI);

    // prep: fp16 splits
    split_x<<<131072, 256>>>(x);
    split_wi<<<6144, 256>>>(Wi);
    // xi = x @ Wi + bi on tensor cores (fp16 2-term)
    xi_mma<<<dim3(48, 512), 256, SMEM_XI>>>(bi, xi_ptr);
    // zero h buffer + barrier
    init_state<<<512, 256>>>();
    // whole 512-step recurrence on tensor cores (fp16 2-term)
    gru_mma_persist<<<NC, 256, SMEM_TOTAL>>>(Wh, bh, out);
}